// round 9
// baseline (speedup 1.0000x reference)
#include <cuda_runtime.h>

// Problem constants (fixed by setup_inputs)
#define M_PTS   1024
#define BATCH   2
#define NC      64
#define KS      13
#define NA      20
#define DOUT    64
#define KP      (KS * NA)          // 260 kernel positions
#define R2      0.16f              // RADIUS^2
// S = -log2(e) / (2*SIGMA) = -1.4426950408889634 / 0.16
#define S_CONST (-9.016844005556021f)
#define M2S     (18.033688011112042f)   // -2*S

#define NAG      4                 // anchor groups per center
#define NA_BLK   (NA / NAG)        // 5 anchors per block
#define KP_BLK   (KS * NA_BLK)     // 65 kernel positions per block
#define TPK      4                 // threads per kernel position

#define NTHREADS 288               // 9 warps; >= KP_BLK*TPK = 260
#define NWARPS   (NTHREADS / 32)
#define NCHUNKS  ((M_PTS + NTHREADS - 1) / NTHREADS)   // 4

__device__ __forceinline__ float ex2(float x) {
    float y;
    asm("ex2.approx.ftz.f32 %0, %1;" : "=f"(y) : "f"(x));
    return y;
}

__global__ __launch_bounds__(NTHREADS, 2)
void kp_fused_kernel(const float* __restrict__ frag,      // (M,3)
                     const float* __restrict__ clouds,    // (B,3,NC)
                     const float* __restrict__ kernels,   // (KS,NA,3) -> [KP][3]
                     const float* __restrict__ W,         // (DOUT,KS)
                     float* __restrict__ out)             // (B,DOUT,NC,NA)
{
    __shared__ float4 s_pts[M_PTS];      // {rx, ry, rz, ex2(S*|r|^2)}
    __shared__ float  s_wts[KP_BLK];     // [k*NA_BLK + a_local]
    __shared__ float  s_W[DOUT * KS];
    __shared__ int    s_wcnt[NCHUNKS][NWARPS];

    const int tid  = threadIdx.x;
    const int lane = tid & 31;
    const int wrp  = tid >> 5;

    const int blk  = blockIdx.x;
    const int bidx = blk / NAG;          // center index: b*NC + n
    const int ag   = blk % NAG;          // anchor group
    const int bb   = bidx >> 6;          // / NC
    const int n    = bidx & 63;          // % NC
    const int a0   = ag * NA_BLK;

    // 4 threads per kernel position; padded threads duplicate kp 0.
    const int  par   = tid & 3;
    int        kpl   = tid >> 2;               // 0..71, valid < 65
    const bool valid = (kpl < KP_BLK);
    if (!valid) kpl = 0;
    const int  kidx  = kpl / NA_BLK;           // ks index
    const int  aidx  = kpl - kidx * NA_BLK;    // local anchor
    const int  kpg   = kidx * NA + (a0 + aidx);
    const float kx = kernels[3 * kpg + 0];
    const float ky = kernels[3 * kpg + 1];
    const float kz = kernels[3 * kpg + 2];

    const float cx = clouds[bb * 3 * NC + 0 * NC + n];
    const float cy = clouds[bb * 3 * NC + 1 * NC + n];
    const float cz = clouds[bb * 3 * NC + 2 * NC + n];

    // Preload conv weights into shared (tiny, overlaps phase 1)
    for (int i = tid; i < DOUT * KS; i += NTHREADS) s_W[i] = W[i];

    // ---------------- Phase 1: deterministic in-ball compaction ----------------
    int base = 0;
    #pragma unroll
    for (int chunk = 0; chunk < NCHUNKS; chunk++) {
        const int i = chunk * NTHREADS + tid;
        bool pred = false;
        float rx = 0.f, ry = 0.f, rz = 0.f, rn2 = 0.f;
        if (i < M_PTS) {
            rx = frag[3 * i + 0] - cx;
            ry = frag[3 * i + 1] - cy;
            rz = frag[3 * i + 2] - cz;
            rn2 = fmaf(rz, rz, fmaf(ry, ry, rx * rx));
            pred = rn2 < R2;
        }
        const unsigned bal = __ballot_sync(0xffffffffu, pred);
        if (lane == 0) s_wcnt[chunk][wrp] = __popc(bal);
        __syncthreads();
        int prefix = 0, total = 0;
        #pragma unroll
        for (int w = 0; w < NWARPS; w++) {
            const int c = s_wcnt[chunk][w];
            if (w < wrp) prefix += c;
            total += c;
        }
        if (pred) {
            const int pos = base + prefix + __popc(bal & ((1u << lane) - 1u));
            s_pts[pos] = make_float4(rx, ry, rz, ex2(rn2 * S_CONST));
        }
        base += total;   // identical running total in every thread
    }
    const int cnt = base;   // == nnctn for this center
    __syncthreads();

    // ------- Phase 2: gaussian accumulation, 4 threads per kernel position -----
    {
        const float ps = fmaf(kz, kz, fmaf(ky, ky, kx * kx)) * S_CONST;

        float a0s = 0.f, a1s = 0.f, a2s = 0.f, a3s = 0.f;
        int i = par;
        for (; i + 12 < cnt; i += 16) {
            const float4 r0 = s_pts[i + 0];
            const float4 r1 = s_pts[i + 4];
            const float4 r2 = s_pts[i + 8];
            const float4 r3 = s_pts[i + 12];
            const float d0 = fmaf(r0.z, kz, fmaf(r0.y, ky, r0.x * kx));
            const float d1 = fmaf(r1.z, kz, fmaf(r1.y, ky, r1.x * kx));
            const float d2 = fmaf(r2.z, kz, fmaf(r2.y, ky, r2.x * kx));
            const float d3 = fmaf(r3.z, kz, fmaf(r3.y, ky, r3.x * kx));
            a0s = fmaf(r0.w, ex2(fmaf(d0, M2S, ps)), a0s);
            a1s = fmaf(r1.w, ex2(fmaf(d1, M2S, ps)), a1s);
            a2s = fmaf(r2.w, ex2(fmaf(d2, M2S, ps)), a2s);
            a3s = fmaf(r3.w, ex2(fmaf(d3, M2S, ps)), a3s);
        }
        for (; i < cnt; i += 4) {
            const float4 r0 = s_pts[i];
            const float d0 = fmaf(r0.z, kz, fmaf(r0.y, ky, r0.x * kx));
            a0s = fmaf(r0.w, ex2(fmaf(d0, M2S, ps)), a0s);
        }
        float sum = (a0s + a1s) + (a2s + a3s);
        // combine the 4 partner lanes (lane-adjacent groups of 4)
        sum += __shfl_xor_sync(0xffffffffu, sum, 1);
        sum += __shfl_xor_sync(0xffffffffu, sum, 2);
        if (valid && par == 0)
            s_wts[kpl] = __fdividef(sum, (float)cnt + 1.0f);
    }
    __syncthreads();

    // ---------------- Phase 3: 1x1 SO3 conv + store ----------------------------
    // feats[b,o,n,a0+al] = sum_k W[o,k] * wts[k*NA_BLK + al]
    #pragma unroll
    for (int oa = tid; oa < DOUT * NA_BLK; oa += NTHREADS) {
        const int o  = oa / NA_BLK;
        const int al = oa % NA_BLK;
        float s = 0.f;
        #pragma unroll
        for (int k = 0; k < KS; k++)
            s = fmaf(s_W[o * KS + k], s_wts[k * NA_BLK + al], s);
        out[(bb * DOUT + o) * (NC * NA) + n * NA + (a0 + al)] = s;
    }
}

extern "C" void kernel_launch(void* const* d_in, const int* in_sizes, int n_in,
                              void* d_out, int out_size) {
    const float* frag    = (const float*)d_in[0];   // (1024,3)
    const float* clouds  = (const float*)d_in[1];   // (2,3,64)
    const float* kernels = (const float*)d_in[2];   // (13,20,3)
    const float* W       = (const float*)d_in[3];   // (64,13)
    float* out = (float*)d_out;                     // (2,64,64,20)

    kp_fused_kernel<<<BATCH * NC * NAG, NTHREADS>>>(frag, clouds, kernels, W, out);
}

// round 10
// speedup vs baseline: 1.0931x; 1.0931x over previous
#include <cuda_runtime.h>

// Problem constants (fixed by setup_inputs)
#define M_PTS   1024
#define BATCH   2
#define NC      64
#define NCEN    (BATCH * NC)       // 128 centers
#define KS      13
#define NA      20
#define DOUT    64
#define KP      (KS * NA)          // 260 kernel positions
#define R2      0.16f              // RADIUS^2
// S = -log2(e) / (2*SIGMA) = -1.4426950408889634 / 0.16
#define S_CONST (-9.016844005556021f)
#define M2S     (18.033688011112042f)   // -2*S

#define Q        4                 // point-quarters per center
#define PTS_BLK  (M_PTS / Q)       // 256 points per block

#define NT1      320               // K1 threads (10 warps)
#define NW1      (NT1 / 32)
#define NT2      288               // K2 threads

// Fixed-slot scratch: deterministic combine, no atomics, no allocation.
__device__ float g_partial[NCEN][Q][KP];
__device__ int   g_cnt[NCEN][Q];

__device__ __forceinline__ float ex2(float x) {
    float y;
    asm("ex2.approx.ftz.f32 %0, %1;" : "=f"(y) : "f"(x));
    return y;
}

// ===================== K1: per-quarter gaussian partial sums =====================
__global__ __launch_bounds__(NT1, 4)
void kp_gauss_kernel(const float* __restrict__ frag,      // (M,3)
                     const float* __restrict__ clouds,    // (B,3,NC)
                     const float* __restrict__ kernels)   // (KS,NA,3) -> [KP][3]
{
    __shared__ float4 s_pts[PTS_BLK];    // {rx, ry, rz, ex2(S*|r|^2)}
    __shared__ int    s_wcnt[NW1];

    const int tid  = threadIdx.x;
    const int lane = tid & 31;
    const int wrp  = tid >> 5;

    const int blk    = blockIdx.x;
    const int center = blk >> 2;         // / Q
    const int q      = blk & 3;          // % Q
    const int bb     = center >> 6;      // / NC
    const int n      = center & 63;      // % NC

    // kernel position for this thread (1 thread per KP)
    const bool valid = (tid < KP);
    const int  kp    = valid ? tid : 0;
    const float kx = kernels[3 * kp + 0];
    const float ky = kernels[3 * kp + 1];
    const float kz = kernels[3 * kp + 2];

    const float cx = clouds[bb * 3 * NC + 0 * NC + n];
    const float cy = clouds[bb * 3 * NC + 1 * NC + n];
    const float cz = clouds[bb * 3 * NC + 2 * NC + n];

    // ---- compaction of this block's 256-point quarter (single chunk) ----
    const int i = q * PTS_BLK + tid;     // threads 256..319 -> pred false
    bool pred = false;
    float rx = 0.f, ry = 0.f, rz = 0.f, rn2 = 0.f;
    if (tid < PTS_BLK) {
        rx = frag[3 * i + 0] - cx;
        ry = frag[3 * i + 1] - cy;
        rz = frag[3 * i + 2] - cz;
        rn2 = fmaf(rz, rz, fmaf(ry, ry, rx * rx));
        pred = rn2 < R2;
    }
    const unsigned bal = __ballot_sync(0xffffffffu, pred);
    if (lane == 0) s_wcnt[wrp] = __popc(bal);
    __syncthreads();
    int prefix = 0, cnt = 0;
    #pragma unroll
    for (int w = 0; w < NW1; w++) {
        const int c = s_wcnt[w];
        if (w < wrp) prefix += c;
        cnt += c;
    }
    if (pred) {
        const int pos = prefix + __popc(bal & ((1u << lane) - 1u));
        s_pts[pos] = make_float4(rx, ry, rz, ex2(rn2 * S_CONST));
    }
    __syncthreads();

    if (tid == 0) g_cnt[center][q] = cnt;

    // ---- gaussian partial accumulation over the quarter-list ----
    if (valid) {
        const float ps = fmaf(kz, kz, fmaf(ky, ky, kx * kx)) * S_CONST;

        float a0 = 0.f, a1 = 0.f, a2 = 0.f, a3 = 0.f;
        int j = 0;
        for (; j + 3 < cnt; j += 4) {
            const float4 r0 = s_pts[j + 0];
            const float4 r1 = s_pts[j + 1];
            const float4 r2 = s_pts[j + 2];
            const float4 r3 = s_pts[j + 3];
            const float d0 = fmaf(r0.z, kz, fmaf(r0.y, ky, r0.x * kx));
            const float d1 = fmaf(r1.z, kz, fmaf(r1.y, ky, r1.x * kx));
            const float d2 = fmaf(r2.z, kz, fmaf(r2.y, ky, r2.x * kx));
            const float d3 = fmaf(r3.z, kz, fmaf(r3.y, ky, r3.x * kx));
            a0 = fmaf(r0.w, ex2(fmaf(d0, M2S, ps)), a0);
            a1 = fmaf(r1.w, ex2(fmaf(d1, M2S, ps)), a1);
            a2 = fmaf(r2.w, ex2(fmaf(d2, M2S, ps)), a2);
            a3 = fmaf(r3.w, ex2(fmaf(d3, M2S, ps)), a3);
        }
        for (; j < cnt; j++) {
            const float4 r0 = s_pts[j];
            const float d0 = fmaf(r0.z, kz, fmaf(r0.y, ky, r0.x * kx));
            a0 = fmaf(r0.w, ex2(fmaf(d0, M2S, ps)), a0);
        }
        g_partial[center][q][kp] = (a0 + a1) + (a2 + a3);
    }
}

// ===================== K2: combine + divide + 1x1 SO3 conv =====================
__global__ __launch_bounds__(NT2, 4)
void kp_conv_kernel(const float* __restrict__ W,          // (DOUT,KS)
                    float* __restrict__ out)              // (B,DOUT,NC,NA)
{
    __shared__ float s_wts[KP];
    __shared__ float s_W[DOUT * KS];

    const int tid    = threadIdx.x;
    const int center = blockIdx.x;
    const int bb     = center >> 6;
    const int n      = center & 63;

    for (int idx = tid; idx < DOUT * KS; idx += NT2) s_W[idx] = W[idx];

    if (tid < KP) {
        // fixed combine order -> deterministic
        const float s = ((g_partial[center][0][tid] + g_partial[center][1][tid]) +
                         (g_partial[center][2][tid] + g_partial[center][3][tid]));
        const int cnt = ((g_cnt[center][0] + g_cnt[center][1]) +
                         (g_cnt[center][2] + g_cnt[center][3]));
        s_wts[tid] = __fdividef(s, (float)cnt + 1.0f);
    }
    __syncthreads();

    // feats[b,o,n,a] = sum_k W[o,k] * wts[k*NA + a]
    for (int oa = tid; oa < DOUT * NA; oa += NT2) {
        const int o = oa / NA;
        const int a = oa % NA;
        float s = 0.f;
        #pragma unroll
        for (int k = 0; k < KS; k++)
            s = fmaf(s_W[o * KS + k], s_wts[k * NA + a], s);
        out[(bb * DOUT + o) * (NC * NA) + n * NA + a] = s;
    }
}

extern "C" void kernel_launch(void* const* d_in, const int* in_sizes, int n_in,
                              void* d_out, int out_size) {
    const float* frag    = (const float*)d_in[0];   // (1024,3)
    const float* clouds  = (const float*)d_in[1];   // (2,3,64)
    const float* kernels = (const float*)d_in[2];   // (13,20,3)
    const float* W       = (const float*)d_in[3];   // (64,13)
    float* out = (float*)d_out;                     // (2,64,64,20)

    kp_gauss_kernel<<<NCEN * Q, NT1>>>(frag, clouds, kernels);
    kp_conv_kernel<<<NCEN, NT2>>>(W, out);
}